// round 16
// baseline (speedup 1.0000x reference)
#include <cuda_runtime.h>
#include <math.h>

#define BB 4
#define NN 2048
#define CC 81
#define ROWS (BB * NN)          // 8192
#define IMG_W 1024.0f
#define IMG_H 800.0f
#define SCORE_THRESH 0.05f
#define NMS_THRESH 0.5f
#define DETS_PER_IMG 100
#define BBOX_CLIP 4.135166556742356f
#define P_  256                 // NMS mask prefix length
#define WP  (P_ / 64)           // 4 words per prefix row
#define SSEL 512                // selection capacity
#define TSEL 320                // selection target (>= P_ + margin)
#define NTHR 1024               // tail kernel block size

// ---------------- scratch (device globals, no allocation allowed) ----------------
__device__ float  g_score[ROWS];
__device__ float  g_s[ROWS];
__device__ float4 g_lbox[ROWS];
__device__ float4 g_rbox[ROWS];
__device__ int    g_order[ROWS];
__device__ float  g_ssort[ROWS];
__device__ float4 g_sboxL[ROWS];
__device__ float4 g_sboxR[ROWS];
__device__ int    g_nvalid[BB];
__device__ int    g_sv[BB];
__device__ unsigned long long g_mask[(size_t)2 * BB * P_ * WP];   // 64 KB prefix bitmask
__device__ unsigned long long g_nz[2][BB][WP];
__device__ unsigned g_epoch;          // +1 per launch (written by decode kernel)
__device__ unsigned g_sort_done[BB];  // +1 per launch
__device__ unsigned g_mask_done[BB];  // +8 per launch

__device__ __forceinline__ float NEGINF() { return __int_as_float(0xff800000); }

__device__ __forceinline__ void cp_async8(void* dst, const void* src) {
    unsigned d = (unsigned)__cvta_generic_to_shared(dst);
    asm volatile("cp.async.ca.shared.global [%0], [%1], 8;" :: "r"(d), "l"(src));
}
#define CP_COMMIT() asm volatile("cp.async.commit_group;" ::: "memory")
#define CP_WAIT(n)  asm volatile("cp.async.wait_group %0;" :: "n"(n) : "memory")

__device__ __forceinline__ float box_area(float4 a) {
    return fmaxf(__fadd_rn(__fsub_rn(a.z, a.x), 1.0f), 0.0f) *
           fmaxf(__fadd_rn(__fsub_rn(a.w, a.y), 1.0f), 0.0f);
}

__device__ __forceinline__ bool iou_gt(float4 a, float areaA, float4 b) {
    float areaB = box_area(b);
    float lx = fmaxf(a.x, b.x), ly = fmaxf(a.y, b.y);
    float rx = fminf(a.z, b.z), ry = fminf(a.w, b.w);
    float iw = fmaxf(__fadd_rn(__fsub_rn(rx, lx), 1.0f), 0.0f);
    float ih = fmaxf(__fadd_rn(__fsub_rn(ry, ly), 1.0f), 0.0f);
    float inter = __fmul_rn(iw, ih);
    float uni = fmaxf(__fsub_rn(__fadd_rn(areaA, areaB), inter), 1e-6f);
    return __fdiv_rn(inter, uni) > NMS_THRESH;
}

__device__ __forceinline__ float4 decode_clip(float4 r, float4 p, float W1, float H1) {
    float w  = p.z - p.x + 1.0f;
    float h  = p.w - p.y + 1.0f;
    float cx = p.x + 0.5f * w;
    float cy = p.y + 0.5f * h;
    float dx = r.x / 10.0f;
    float dy = r.y / 10.0f;
    float dw = fminf(r.z / 5.0f, BBOX_CLIP);
    float dh = fminf(r.w / 5.0f, BBOX_CLIP);
    float pcx = dx * w + cx;
    float pcy = dy * h + cy;
    float pw = expf(dw) * w;
    float ph = expf(dh) * h;
    float x1 = pcx - 0.5f * pw;
    float y1 = pcy - 0.5f * ph;
    float x2 = pcx + 0.5f * pw - 1.0f;
    float y2 = pcy + 0.5f * ph - 1.0f;
    float4 o;
    o.x = fminf(fmaxf(x1, 0.0f), W1);
    o.y = fminf(fmaxf(y1, 0.0f), H1);
    o.z = fminf(fmaxf(x2, 0.0f), W1);
    o.w = fminf(fmaxf(y2, 0.0f), H1);
    return o;
}

__device__ unsigned long long onfly_row(const float4* boxes, int i, int lane) {
    float4 a = boxes[i];
    float areaA = box_area(a);
    unsigned long long bits = 0;
    int jbase = lane << 6;
    for (int jj = 0; jj < 64; jj++) {
        int j = jbase + jj;
        if (j <= i) continue;
        if (iou_gt(a, areaA, boxes[j])) bits |= (1ull << jj);
    }
    return bits;
}

__device__ __forceinline__ unsigned ordered_u(float s) {
    unsigned u = __float_as_uint(s);
    return (u & 0x80000000u) ? ~u : (u | 0x80000000u);
}
__device__ __forceinline__ unsigned long long sort_key(float s, int idx) {
    return ((unsigned long long)ordered_u(s) << 32) | (unsigned)(0xFFFFFFFFu - (unsigned)idx);
}

// block-wide descending bitonic sort, n power of two (fallback only)
__device__ void bitonic_desc(unsigned long long* k, int n) {
    int tid = threadIdx.x;
    int jp = 32;
    for (int kk = 2; kk <= n; kk <<= 1) {
        for (int j = kk >> 1; j > 0; j >>= 1) {
            if (j >= 32 || jp >= 32) __syncthreads(); else __syncwarp();
            for (int t = tid; t < n; t += NTHR) {
                int ixj = t ^ j;
                if (ixj > t) {
                    unsigned long long a = k[t], b = k[ixj];
                    bool sw = ((t & kk) == 0) ? (a < b) : (a > b);
                    if (sw) { k[t] = b; k[ixj] = a; }
                }
            }
            jp = j;
        }
    }
    __syncthreads();
}

// fallback: full exact sort of all NN positions (block-wide)
__device__ void full_sort_block(int img, unsigned long long* keyF) {
    int tid = threadIdx.x;
    for (int p = tid; p < NN; p += NTHR) keyF[p] = sort_key(g_s[img * NN + p], p);
    __syncthreads();
    bitonic_desc(keyF, NN);
    for (int p = tid; p < NN; p += NTHR) {
        unsigned long long kk = keyF[p];
        int local = (int)(0xFFFFFFFFu - (unsigned)(kk & 0xFFFFFFFFu));
        int g = img * NN + local;
        g_order[img * NN + p] = local;
        g_ssort[img * NN + p] = g_s[g];
        g_sboxL[img * NN + p] = g_lbox[g];
        g_sboxR[img * NN + p] = g_rbox[g];
    }
    __syncthreads();
}

// ================= kernel A: decode (1 row per warp, high occupancy) =================
__global__ void __launch_bounds__(128)
decode_kernel(const float* __restrict__ logits,
              const float* __restrict__ reg,
              const float* __restrict__ lp,
              const float* __restrict__ rp,
              float* __restrict__ out) {
    int tid = threadIdx.x;
    int lane = tid & 31;
    int wid = tid >> 5;
    int row = blockIdx.x * 4 + wid;                      // 2048 blocks x 4 warps = 8192 rows
    int gidx = blockIdx.x * 128 + tid;
    if (gidx < BB * NN * 9) out[gidx] = 0.0f;            // zero output
    if (gidx == 0) atomicAdd(&g_epoch, 1u);              // per-launch epoch bump

    const float* lrow = logits + (size_t)row * CC;
    float v0 = lrow[lane];
    float v1 = lrow[lane + 32];
    float v2 = (lane < CC - 64) ? lrow[lane + 64] : NEGINF();
    float4 pp;
    if (lane == 0)  pp = ((const float4*)lp)[row];       // early proposal loads
    if (lane == 16) pp = ((const float4*)rp)[row];

    unsigned u0 = ordered_u(v0);
    unsigned u1 = ordered_u(v1);
    unsigned u2 = (lane < CC - 64) ? ordered_u(v2) : 0u;
    unsigned um = u0 > u1 ? u0 : u1;
    if (u2 > um) um = u2;
    unsigned m = __reduce_max_sync(0xffffffffu, um);
    int bi;
    unsigned b0 = __ballot_sync(0xffffffffu, u0 == m);
    if (b0) bi = __ffs(b0) - 1;
    else {
        unsigned b1 = __ballot_sync(0xffffffffu, u1 == m);
        if (b1) bi = 32 + __ffs(b1) - 1;
        else {
            unsigned b2 = __ballot_sync(0xffffffffu, u2 == m);
            bi = 64 + __ffs(b2) - 1;
        }
    }
    float bv = __uint_as_float((m & 0x80000000u) ? (m ^ 0x80000000u) : ~m);
    float e = expf(v0 - bv) + expf(v1 - bv) + ((lane < CC - 64) ? expf(v2 - bv) : 0.0f);
    #pragma unroll
    for (int o = 16; o; o >>= 1) e += __shfl_xor_sync(0xffffffffu, e, o);

    if (lane == 0 || lane == 16) {
        float score = __fdiv_rn(1.0f, e);
        const float* rr = reg + (size_t)row * (CC * 8) + bi * 8 + (lane == 16 ? 4 : 0);
        float4 rv = *(const float4*)rr;
        float4 box = decode_clip(rv, pp, IMG_W - 1.0f, IMG_H - 1.0f);
        if (lane == 0) {
            g_lbox[row] = box;
            g_score[row] = score;
            bool valid = (bi >= 1) && (score > SCORE_THRESH);
            g_s[row] = valid ? score : NEGINF();
        } else {
            g_rbox[row] = box;
        }
    }
}

// ================= kernel B: selection -> mask -> early-stop scan (36 blocks) ========
__global__ void __launch_bounds__(NTHR, 1)
tail_kernel(float* __restrict__ out) {
    __shared__ __align__(16) char arena[16384];          // hist / rank dst / fallback keys
    __shared__ unsigned long long keySel[SSEL];          // 4 KB
    __shared__ float4 sj[64];                            // mask role
    __shared__ unsigned long long buf[2][2][64 * WP];    // scan cp.async staging (8 KB)
    __shared__ unsigned long long aliveSh[2][32];
    __shared__ unsigned long long jointSh[32];
    __shared__ int warpTot[32];
    __shared__ float kthSh;
    __shared__ int stopSh, cntSh, cutSh, nSelSh, limitSh, selCntSh, svSh;

    const int blk = blockIdx.x;
    const int tid = threadIdx.x;
    const int lane = tid & 31;
    const int wid = tid >> 5;
    const unsigned E = *(volatile unsigned*)&g_epoch;    // stable during this kernel

    // ---------------- mask blocks (4..35) ----------------
    if (blk >= 4) {
        int idx = blk - 4;
        int side = idx >> 4;
        int img  = (idx >> 2) & 3;
        int w    = idx & 3;
        if (tid == 0) {
            while ((*(volatile unsigned*)&g_sort_done[img]) < E) {}
            __threadfence();
        }
        __syncthreads();
        int limit = g_nvalid[img];
        int jbase = w << 6;
        const float4* boxes = (side == 0 ? g_sboxL : g_sboxR) + img * NN;
        if (jbase < limit) {
            if (tid < 64) sj[tid] = boxes[jbase + tid];
            __syncthreads();
            int ib  = tid >> 8;                          // 0..3
            int r   = (tid >> 2) & 63;
            int subw = tid & 3;
            int i = ib * 64 + r;
            unsigned long long partial = 0;
            if (ib <= w && i < limit) {                  // upper-triangle blocks only
                float4 a = boxes[i];
                float areaA = box_area(a);
                int j0 = subw * 16;
                #pragma unroll
                for (int jj = j0; jj < j0 + 16; jj++) {
                    int j = jbase + jj;
                    if (j <= i) continue;
                    if (iou_gt(a, areaA, sj[jj])) partial |= (1ull << jj);
                }
            }
            partial |= __shfl_xor_sync(0xffffffffu, partial, 1);
            partial |= __shfl_xor_sync(0xffffffffu, partial, 2);
            if (subw == 0 && partial) {
                g_mask[((size_t)(side * BB + img) * P_ + i) * WP + w] = partial;
                atomicOr(&g_nz[side][img][i >> 6], 1ull << (i & 63));
            }
        }
        __threadfence();
        __syncthreads();
        if (tid == 0) atomicAdd(&g_mask_done[img], 1u);
        return;
    }

    // ======== image blocks (0..3): histogram top-K selection -> flag -> scan ========
    const int img = blk;
    int* hist = (int*)arena;
    unsigned long long* keyR = (unsigned long long*)arena;   // rank-sort dest
    unsigned long long* keyF = (unsigned long long*)arena;   // fallback keys (16 KB)

    // ---- histogram of 11-bit ordered-score bins ----
    for (int b = tid; b < 2048; b += NTHR) hist[b] = 0;
    if (tid < WP) { g_nz[0][img][tid] = 0ull; g_nz[1][img][tid] = 0ull; }
    if (tid < 32) { jointSh[tid] = 0; aliveSh[0][tid] = 0; aliveSh[1][tid] = 0; }
    if (tid == 0) { stopSh = 0; cntSh = 0; kthSh = NEGINF(); selCntSh = 0; cutSh = 4; nSelSh = -1; }
    __syncthreads();
    #pragma unroll
    for (int q = 0; q < 2; q++) {
        int p = tid + q * NTHR;
        unsigned u = ordered_u(g_s[img * NN + p]);
        atomicAdd(&hist[u >> 21], 1);
    }
    __syncthreads();

    // ---- hierarchical suffix scan ----
    int h0 = hist[2 * tid], h1 = hist[2 * tid + 1];
    int v = h0 + h1;
    int s = v;
    #pragma unroll
    for (int o = 1; o < 32; o <<= 1) {
        int x = __shfl_down_sync(0xffffffffu, s, o);
        if (lane + o < 32) s += x;
    }
    if (lane == 0) warpTot[wid] = s;
    __syncthreads();
    if (wid == 0) {
        int wv = warpTot[lane];
        int ws = wv;
        #pragma unroll
        for (int o = 1; o < 32; o <<= 1) {
            int x = __shfl_down_sync(0xffffffffu, ws, o);
            if (lane + o < 32) ws += x;
        }
        warpTot[lane] = ws - wv;
    }
    __syncthreads();
    int S = s + warpTot[wid];
    int b0i = 2 * tid;
    if (b0i >= 4 && S >= TSEL && S - h0 < TSEL)            { cutSh = b0i;     nSelSh = S; }
    if (b0i + 1 >= 4 && S - h0 >= TSEL && S - v < TSEL)    { cutSh = b0i + 1; nSelSh = S - h0; }
    if (tid == 2) limitSh = S;
    __syncthreads();
    const int limit = limitSh;
    int nSel = (nSelSh < 0) ? limit : nSelSh;
    if (nSel > limit) nSel = limit;
    const int cut = cutSh;

    if (nSel <= SSEL) {
        #pragma unroll
        for (int q = 0; q < 2; q++) {
            int p = tid + q * NTHR;
            unsigned u = ordered_u(g_s[img * NN + p]);
            if ((int)(u >> 21) >= cut) {
                int slot = atomicAdd(&selCntSh, 1);
                keySel[slot] = ((unsigned long long)u << 32) |
                               (unsigned)(0xFFFFFFFFu - (unsigned)p);
            }
        }
        __syncthreads();
        int n = selCntSh;
        if (tid < n) {                                    // rank sort (keys unique)
            unsigned long long kt = keySel[tid];
            int cnt = 0;
            for (int j = 0; j < n; j++) cnt += (keySel[j] > kt) ? 1 : 0;
            keyR[cnt] = kt;
        }
        __syncthreads();
        for (int p = tid; p < nSel; p += NTHR) {
            unsigned long long kk = keyR[p];
            int local = (int)(0xFFFFFFFFu - (unsigned)(kk & 0xFFFFFFFFu));
            int g = img * NN + local;
            g_order[img * NN + p] = local;
            g_ssort[img * NN + p] = g_s[g];
            g_sboxL[img * NN + p] = g_lbox[g];
            g_sboxR[img * NN + p] = g_rbox[g];
        }
        if (tid == 0) svSh = nSel;
    } else {
        full_sort_block(img, keyF);                      // pathological tie overflow
        if (tid == 0) svSh = NN;
    }
    if (tid == 0) { g_nvalid[img] = limit; g_sv[img] = svSh; }
    __threadfence();
    __syncthreads();
    if (tid == 0) atomicAdd(&g_sort_done[img], 1u);

    // wait for this image's 8 mask blocks
    if (tid == 0) {
        while ((*(volatile unsigned*)&g_mask_done[img]) < 8u * E) {}
        __threadfence();
    }
    __syncthreads();

    // ---------------- early-terminating joint greedy scan ----------------
    unsigned long long alive = 0, nzreg = 0;
    const float4* boxesG = 0;
    const unsigned long long* maskBase = 0;
    if (wid < 2) {
        maskBase = g_mask + (size_t)(wid * BB + img) * P_ * WP;
        boxesG = (wid == 0 ? g_sboxL : g_sboxR) + img * NN;
        nzreg = (lane < WP) ? g_nz[wid][img][lane] : 0ull;
        int lo = lane << 6;
        alive = (limit >= lo + 64) ? ~0ull
              : (limit <= lo ? 0ull : ((1ull << (limit - lo)) - 1ull));
        unsigned long long wk = __shfl_sync(0xffffffffu, alive & nzreg, 0);
        while (wk) {
            int i = __ffsll((long long)wk) - 1; wk &= wk - 1;
            if (lane < WP) cp_async8(&buf[wid][0][i * WP + lane],
                                     maskBase + (size_t)i * WP + lane);
        }
        CP_COMMIT();
    }

    bool missedDone = false;
    for (int w = 0; w < 32; w++) {
        if (w == WP) {       // order needed beyond prefix -> exact full sort (rare)
            if (wid < 2) CP_WAIT(0);
            __syncthreads();
            if (svSh < NN) {
                full_sort_block(img, keyF);
                if (tid == 0) svSh = NN;
            }
            __syncthreads();
        }
        if (wid < 2) {
            if (w < WP) {
                if (w + 1 < WP) {
                    unsigned long long wk = __shfl_sync(0xffffffffu, alive & nzreg, w + 1);
                    unsigned long long* nb = buf[wid][(w + 1) & 1];
                    while (wk) {
                        int i = __ffsll((long long)wk) - 1; wk &= wk - 1;
                        if (lane < WP)
                            cp_async8(&nb[i * WP + lane],
                                      maskBase + (size_t)((w + 1) * 64 + i) * WP + lane);
                    }
                    CP_COMMIT(); CP_WAIT(1);
                } else {
                    CP_WAIT(0);
                }
                __syncwarp();
                unsigned long long work = __shfl_sync(0xffffffffu, alive & nzreg, w);
                unsigned long long* cur = buf[wid][w & 1];
                unsigned long long supp = 0;
                while (work) {
                    int i = __ffsll((long long)work) - 1;
                    work &= work - 1;
                    unsigned long long rv = (lane < WP) ? cur[i * WP + lane] : 0ull;
                    unsigned long long ww = cur[i * WP + w];
                    supp |= rv;
                    work &= ~ww;
                }
                alive &= ~supp;
            } else {
                if (!missedDone) {
                    missedDone = true;
                    for (int pw = 0; pw < WP; pw++) {
                        unsigned long long kk = __shfl_sync(0xffffffffu, alive, pw);
                        while (kk) {
                            int ii = __ffsll((long long)kk) - 1; kk &= kk - 1;
                            unsigned long long ww = onfly_row(boxesG, pw * 64 + ii, lane);
                            if (lane >= WP) alive &= ~ww;
                        }
                    }
                }
                unsigned long long work = __shfl_sync(0xffffffffu, alive, w);
                unsigned long long supp = 0;
                while (work) {
                    int i = __ffsll((long long)work) - 1;
                    work &= work - 1;
                    unsigned long long ww = onfly_row(boxesG, w * 64 + i, lane);
                    supp |= ww;
                    unsigned long long www = __shfl_sync(0xffffffffu, ww, w);
                    work &= ~www;
                }
                alive &= ~supp;
            }
            if (lane == w) aliveSh[wid][w] = alive;
        }
        __syncthreads();
        if (tid == 0) {
            unsigned long long jw = aliveSh[0][w] & aliveSh[1][w];
            jointSh[w] = jw;
            int pc = __popcll(jw);
            int cnt = cntSh;
            if (cnt < DETS_PER_IMG && cnt + pc >= DETS_PER_IMG) {
                int need = DETS_PER_IMG - cnt;
                unsigned long long t = jw; int b = -1;
                while (need--) { b = __ffsll((long long)t) - 1; t &= t - 1; }
                kthSh = g_ssort[img * NN + w * 64 + b];
            }
            cnt += pc; cntSh = cnt;
            int nxt = (w + 1) * 64;
            bool fin = (nxt >= limit);
            if (!fin && cnt >= DETS_PER_IMG && nxt < svSh &&
                g_ssort[img * NN + nxt] < kthSh) fin = true;
            stopSh = fin ? 1 : 0;
        }
        __syncthreads();
        if (stopSh) break;
    }
    if (wid < 2) CP_WAIT(0);

    float kth = kthSh;
    for (int p = tid; p < NN; p += NTHR) {
        if (!((jointSh[p >> 6] >> (p & 63)) & 1ull)) continue;
        float s2 = g_ssort[img * NN + p];
        if (s2 >= kth) {
            int g = img * NN + g_order[img * NN + p];
            float4 lb = g_lbox[g], rb = g_rbox[g];
            float* o = out + (size_t)g * 9;
            o[0] = lb.x; o[1] = lb.y; o[2] = lb.z; o[3] = lb.w;
            o[4] = rb.x; o[5] = rb.y; o[6] = rb.z; o[7] = rb.w;
            o[8] = g_score[g];
        }
    }
}

// ---------------- launch ----------------
extern "C" void kernel_launch(void* const* d_in, const int* in_sizes, int n_in,
                              void* d_out, int out_size) {
    const float* logits = (const float*)d_in[0];
    const float* reg    = (const float*)d_in[1];
    const float* lp     = (const float*)d_in[2];
    const float* rp     = (const float*)d_in[3];
    float* out = (float*)d_out;
    decode_kernel<<<ROWS / 4, 128>>>(logits, reg, lp, rp, out);
    tail_kernel<<<36, NTHR>>>(out);
}